// round 16
// baseline (speedup 1.0000x reference)
#include <cuda_runtime.h>
#include <cuda_fp16.h>
#include <math.h>

// Problem constants
#define BB 2
#define SS 2048
#define HH 1024
#define NHEADS 16
#define DH 64
#define MM (BB * SS)   // 4096 rows
#define LOG2E 1.44269504088896f

// ---------------- scratch (device globals; no allocation allowed) -----------
__device__ __half g_qh[MM * HH];      // projected Q/K/V (fp16)
__device__ __half g_kh[MM * HH];
__device__ __half g_vh[MM * HH];
__device__ __half g_ch[MM * HH];      // flash output ctx (fp16)
__device__ __half g_xq[MM * HH];      // converted activations
__device__ __half g_xk[MM * HH];
__device__ __half g_xv[MM * HH];
__device__ __half g_wqh[HH * HH];     // converted weights [k][n]
__device__ __half g_wkh[HH * HH];
__device__ __half g_wvh[HH * HH];
__device__ __half g_woh[HH * HH];
__device__ __half g_mh[BB * SS * SS]; // mask * log2e, fp16

// ---------------- helpers ----------------------------------------------------
__device__ __forceinline__ void mma_f16(float c[4],
                                        unsigned a0, unsigned a1,
                                        unsigned a2, unsigned a3,
                                        unsigned b0, unsigned b1) {
    asm volatile(
        "mma.sync.aligned.m16n8k16.row.col.f32.f16.f16.f32 "
        "{%0,%1,%2,%3}, {%4,%5,%6,%7}, {%8,%9}, {%0,%1,%2,%3};"
        : "+f"(c[0]), "+f"(c[1]), "+f"(c[2]), "+f"(c[3])
        : "r"(a0), "r"(a1), "r"(a2), "r"(a3), "r"(b0), "r"(b1));
}

__device__ __forceinline__ void ldsm4(unsigned& d0, unsigned& d1,
                                      unsigned& d2, unsigned& d3, unsigned a) {
    asm volatile("ldmatrix.sync.aligned.m8n8.x4.shared.b16 {%0,%1,%2,%3}, [%4];"
                 : "=r"(d0), "=r"(d1), "=r"(d2), "=r"(d3) : "r"(a));
}
__device__ __forceinline__ void ldsm4t(unsigned& d0, unsigned& d1,
                                       unsigned& d2, unsigned& d3, unsigned a) {
    asm volatile("ldmatrix.sync.aligned.m8n8.x4.trans.shared.b16 {%0,%1,%2,%3}, [%4];"
                 : "=r"(d0), "=r"(d1), "=r"(d2), "=r"(d3) : "r"(a));
}

__device__ __forceinline__ void cpa16(unsigned sdst, const void* gsrc) {
    asm volatile("cp.async.cg.shared.global [%0], [%1], 16;"
                 :: "r"(sdst), "l"(gsrc));
}
__device__ __forceinline__ void cpa_commit() {
    asm volatile("cp.async.commit_group;");
}
__device__ __forceinline__ void cpa_wait1() {
    asm volatile("cp.async.wait_group 1;");
}

__device__ __forceinline__ unsigned packh2(float x, float y) {
    __half2 h = __floats2half2_rn(x, y);
    return *(unsigned*)&h;
}
__device__ __forceinline__ unsigned hadd2u(unsigned a, unsigned b) {
    unsigned d;
    asm("add.f16x2 %0, %1, %2;" : "=r"(d) : "r"(a), "r"(b));
    return d;
}
__device__ __forceinline__ unsigned ex2h2(unsigned a) {
    unsigned d;
    asm("ex2.approx.f16x2 %0, %1;" : "=r"(d) : "r"(a));
    return d;
}

// ---------------- prepass: fp32 -> fp16 (7 tensors, one launch) --------------
__global__ __launch_bounds__(256) void f2h_all(
    const float4* i0, const float4* i1, const float4* i2, const float4* i3,
    const float4* i4, const float4* i5, const float4* i6,
    uint2* o0, uint2* o1, uint2* o2, uint2* o3,
    uint2* o4, uint2* o5, uint2* o6,
    int nact4, int nw4)
{
    const int seg = blockIdx.y;
    const float4* in;
    uint2* out;
    int n4;
    switch (seg) {
        case 0: in = i0; out = o0; n4 = nact4; break;
        case 1: in = i1; out = o1; n4 = nact4; break;
        case 2: in = i2; out = o2; n4 = nact4; break;
        case 3: in = i3; out = o3; n4 = nw4; break;
        case 4: in = i4; out = o4; n4 = nw4; break;
        case 5: in = i5; out = o5; n4 = nw4; break;
        default: in = i6; out = o6; n4 = nw4; break;
    }
    int i = blockIdx.x * 256 + threadIdx.x;
    if (i < n4) {
        float4 v = in[i];
        __half2 h0 = __floats2half2_rn(v.x, v.y);
        __half2 h1 = __floats2half2_rn(v.z, v.w);
        out[i] = make_uint2(*(unsigned*)&h0, *(unsigned*)&h1);
    }
}

// mask -> fp16, pre-scaled by log2e (exp2 domain)
__global__ __launch_bounds__(256) void mask2h(const float4* __restrict__ in,
                                              uint2* __restrict__ out, int n4)
{
    int i = blockIdx.x * 256 + threadIdx.x;
    if (i < n4) {
        float4 v = in[i];
        __half2 h0 = __floats2half2_rn(v.x * LOG2E, v.y * LOG2E);
        __half2 h1 = __floats2half2_rn(v.z * LOG2E, v.w * LOG2E);
        out[i] = make_uint2(*(unsigned*)&h0, *(unsigned*)&h1);
    }
}

// ---------------- fp16 GEMM body (Round-13 proven) ---------------------------
#define G2BK 32
#define A2STR 40
#define B2STR 136
#define ABUFB (128 * A2STR * 2)
#define BBUFB (G2BK * B2STR * 2)
#define GEMM2_SMEM (2 * ABUFB + 2 * BBUFB)

__device__ __forceinline__ void gemm_body(
    const __half* __restrict__ A, const __half* __restrict__ W,
    const float* __restrict__ bias, float* __restrict__ Cf,
    __half* __restrict__ Ch, float scale)
{
    extern __shared__ __half gsm2[];
    const unsigned sbA = (unsigned)__cvta_generic_to_shared(gsm2);
    const unsigned sbB = sbA + 2 * ABUFB;

    const int tid = threadIdx.x;
    const int lane = tid & 31;
    const int wid = tid >> 5;
    const int wm = (wid & 1) * 64;
    const int wn = (wid >> 1) * 32;
    const int r4 = lane >> 2;
    const int c4 = lane & 3;
    const int bm = blockIdx.y * 128;
    const int bn = blockIdx.x * 128;

    const int arow = tid >> 1;
    const int acol = (tid & 1) * 16;
    const int brow = tid >> 3;
    const int bcol = (tid & 7) * 16;

    const int bsel = lane >> 3;
    const int l7 = lane & 7;
    const unsigned aOff = (unsigned)(((8 * (bsel & 1) + l7) * A2STR + 8 * (bsel >> 1)) * 2);
    const unsigned bOff = (unsigned)(((8 * (bsel & 1) + l7) * B2STR + 8 * (bsel >> 1)) * 2);

    const __half* asrc = &A[(size_t)(bm + arow) * HH + acol];
    const __half* bsrc = &W[(size_t)brow * HH + bn + bcol];

    float acc[16][4];
#pragma unroll
    for (int i = 0; i < 16; i++)
#pragma unroll
        for (int j = 0; j < 4; j++) acc[i][j] = 0.0f;

    const int nk = HH / G2BK;

    {
        const unsigned dA = sbA + (unsigned)((arow * A2STR + acol) * 2);
        const unsigned dB = sbB + (unsigned)((brow * B2STR + bcol) * 2);
        cpa16(dA, asrc);       cpa16(dA + 16, asrc + 8);
        cpa16(dB, bsrc);       cpa16(dB + 16, bsrc + 8);
        cpa_commit();
    }

    for (int kt = 0; kt < nk; kt++) {
        if (kt + 1 < nk) {
            const int k0 = (kt + 1) * G2BK;
            const int nb = (kt + 1) & 1;
            const unsigned dA = sbA + (unsigned)(nb * ABUFB + (arow * A2STR + acol) * 2);
            const unsigned dB = sbB + (unsigned)(nb * BBUFB + (brow * B2STR + bcol) * 2);
            cpa16(dA, asrc + k0);       cpa16(dA + 16, asrc + k0 + 8);
            const __half* bs = &W[(size_t)(k0 + brow) * HH + bn + bcol];
            cpa16(dB, bs);              cpa16(dB + 16, bs + 8);
        }
        cpa_commit();
        cpa_wait1();
        __syncthreads();

        const unsigned abuf = sbA + (unsigned)((kt & 1) * ABUFB);
        const unsigned bbuf = sbB + (unsigned)((kt & 1) * BBUFB);

#pragma unroll
        for (int s = 0; s < 2; s++) {
            unsigned bf[2][4];
#pragma unroll
            for (int p = 0; p < 2; p++)
                ldsm4t(bf[p][0], bf[p][1], bf[p][2], bf[p][3],
                       bbuf + (unsigned)((s * 16 * B2STR + wn + p * 16) * 2) + bOff);
#pragma unroll
            for (int mt = 0; mt < 4; mt++) {
                unsigned a0, a1, a2, a3;
                ldsm4(a0, a1, a2, a3,
                      abuf + (unsigned)(((wm + mt * 16) * A2STR + s * 16) * 2) + aOff);
#pragma unroll
                for (int p = 0; p < 2; p++) {
                    mma_f16(acc[mt * 4 + 2 * p],     a0, a1, a2, a3, bf[p][0], bf[p][1]);
                    mma_f16(acc[mt * 4 + 2 * p + 1], a0, a1, a2, a3, bf[p][2], bf[p][3]);
                }
            }
        }
        __syncthreads();
    }

#pragma unroll
    for (int mt = 0; mt < 4; mt++) {
#pragma unroll
        for (int nt = 0; nt < 4; nt++) {
            const int row0 = bm + wm + mt * 16 + r4;
            const int col = bn + wn + nt * 8 + 2 * c4;
            const float b0 = bias[col], b1 = bias[col + 1];
            float v00 = (acc[mt * 4 + nt][0] + b0) * scale;
            float v01 = (acc[mt * 4 + nt][1] + b1) * scale;
            float v10 = (acc[mt * 4 + nt][2] + b0) * scale;
            float v11 = (acc[mt * 4 + nt][3] + b1) * scale;
            if (Ch) {
                *(__half2*)&Ch[(size_t)row0 * HH + col] = __floats2half2_rn(v00, v01);
                *(__half2*)&Ch[(size_t)(row0 + 8) * HH + col] = __floats2half2_rn(v10, v11);
            } else {
                float* c0 = &Cf[(size_t)row0 * HH + col];
                float* c1 = &Cf[(size_t)(row0 + 8) * HH + col];
                c0[0] = v00; c0[1] = v01;
                c1[0] = v10; c1[1] = v11;
            }
        }
    }
}

// fused Q/K/V projection. Q folds 0.125*log2e (exp2-domain softmax).
__global__ __launch_bounds__(256) void gemm_qkv(
    const __half* Aq, const __half* Ak, const __half* Av,
    const __half* Wq, const __half* Wk, const __half* Wv,
    const float* bq, const float* bk, const float* bv,
    __half* Cq, __half* Ck, __half* Cv)
{
    const int z = blockIdx.z;
    const __half* A = (z == 0) ? Aq : (z == 1) ? Ak : Av;
    const __half* W = (z == 0) ? Wq : (z == 1) ? Wk : Wv;
    const float* bias = (z == 0) ? bq : (z == 1) ? bk : bv;
    __half* C = (z == 0) ? Cq : (z == 1) ? Ck : Cv;
    gemm_body(A, W, bias, nullptr, C, (z == 0) ? 0.125f * LOG2E : 1.0f);
}

__global__ __launch_bounds__(256) void gemm_out(
    const __half* A, const __half* W, const float* bias, float* C)
{
    gemm_body(A, W, bias, C, nullptr, 1.0f);
}

// ---------------- Flash attention (fp16, exp2-domain, half2 softmax) ---------
// Scores arrive in log2 domain (Q pre-scaled, mask pre-scaled fp16).
// Per tile: pack -> HADD2 mask -> ex2.f16x2 (16 MUFU) -> P regs ARE the PV
// A-frags. Row sums via an extra ones-column mma (tensor pipe, fp32 accum).
#define FBQ 128
#define HSTR 72
#define KHALF (64 * HSTR)
#define FLASH_SMEM (4 * KHALF * 2)   // 2 K buffers + 2 V buffers

__global__ __launch_bounds__(256, 2) void flash_f16(
    const __half* __restrict__ Q, const __half* __restrict__ K,
    const __half* __restrict__ V, const __half* __restrict__ maskh,
    __half* __restrict__ Ctxh)
{
    extern __shared__ __half hsm[];
    const unsigned sbK = (unsigned)__cvta_generic_to_shared(hsm);
    const unsigned sbV = sbK + 2 * KHALF * 2;

    const int tid = threadIdx.x;
    const int lane = tid & 31;
    const int w = tid >> 5;
    const int r4 = lane >> 2;
    const int c4 = lane & 3;
    const int qb = blockIdx.x * FBQ;
    const int h = blockIdx.y;
    const int b = blockIdx.z;

    const size_t base = (size_t)b * SS * HH;
    const int hoff = h * DH;
    const __half* maskb = maskh + (size_t)b * SS * SS;

    const int srow = tid >> 2;
    const int scol = (tid & 3) * 16;

    const int bsel = lane >> 3;
    const int l7 = lane & 7;
    const unsigned kOff = (unsigned)(((8 * (bsel >> 1) + l7) * HSTR + 8 * (bsel & 1)) * 2);
    const unsigned vOff = (unsigned)(((8 * (bsel & 1) + l7) * HSTR + 8 * (bsel >> 1)) * 2);

    // ones-column B fragment for row-sum mma (n==0 column = 1.0)
    const unsigned ub = (r4 == 0) ? 0x3C003C00u : 0u;

    {
        const __half* kp = &K[base + (size_t)srow * HH + hoff + scol];
        const __half* vp = &V[base + (size_t)srow * HH + hoff + scol];
        const unsigned d = (unsigned)((srow * HSTR + scol) * 2);
        cpa16(sbK + d, kp);       cpa16(sbK + d + 16, kp + 8);
        cpa16(sbV + d, vp);       cpa16(sbV + d + 16, vp + 8);
        cpa_commit();
    }

    unsigned qf[4][4];
    {
        const size_t R0 = base + (size_t)(qb + 16 * w + r4) * HH + hoff;
#pragma unroll
        for (int ks = 0; ks < 4; ks++) {
            const int col = 16 * ks + 2 * c4;
            qf[ks][0] = *(const unsigned*)&Q[R0 + col];
            qf[ks][1] = *(const unsigned*)&Q[R0 + 8 * HH + col];
            qf[ks][2] = *(const unsigned*)&Q[R0 + col + 8];
            qf[ks][3] = *(const unsigned*)&Q[R0 + 8 * HH + col + 8];
        }
    }

    float oc[8][4];
#pragma unroll
    for (int nt = 0; nt < 8; nt++)
#pragma unroll
        for (int j = 0; j < 4; j++) oc[nt][j] = 0.0f;
    float lsum[4] = {0.0f, 0.0f, 0.0f, 0.0f};

    const int NT = SS / 64;
    for (int t = 0; t < NT; t++) {
        const int k0 = t * 64;
        const unsigned kbufB = (unsigned)((t & 1) * KHALF * 2);

        if (t + 1 < NT) {
            const unsigned nbB = (unsigned)(((t + 1) & 1) * KHALF * 2);
            const __half* kp = &K[base + (size_t)(k0 + 64 + srow) * HH + hoff + scol];
            const __half* vp = &V[base + (size_t)(k0 + 64 + srow) * HH + hoff + scol];
            const unsigned d = (unsigned)((srow * HSTR + scol) * 2);
            cpa16(sbK + nbB + d, kp);   cpa16(sbK + nbB + d + 16, kp + 8);
            cpa16(sbV + nbB + d, vp);   cpa16(sbV + nbB + d + 16, vp + 8);
        }
        cpa_commit();
        cpa_wait1();
        __syncthreads();

        // ---- S = Q @ K^T (log2 domain) ----
        float sc[8][4];
#pragma unroll
        for (int nt = 0; nt < 8; nt++)
#pragma unroll
            for (int j = 0; j < 4; j++) sc[nt][j] = 0.0f;

#pragma unroll
        for (int ks = 0; ks < 4; ks++) {
#pragma unroll
            for (int j = 0; j < 4; j++) {
                unsigned b0, b1, b2, b3;
                ldsm4(b0, b1, b2, b3,
                      sbK + kbufB + (unsigned)((j * 16 * HSTR + 16 * ks) * 2) + kOff);
                mma_f16(sc[2 * j],     qf[ks][0], qf[ks][1], qf[ks][2], qf[ks][3], b0, b1);
                mma_f16(sc[2 * j + 1], qf[ks][0], qf[ks][1], qf[ks][2], qf[ks][3], b2, b3);
            }
        }

        // ---- pack + fp16 mask add + exp2 in half2 -> P fragments ----
        unsigned e_lo[8], e_hi[8];
        {
            const size_t mb0 = (size_t)(qb + 16 * w + r4) * SS + k0 + 2 * c4;
            const size_t mb1 = mb0 + (size_t)8 * SS;
#pragma unroll
            for (int nt = 0; nt < 8; nt++) {
                unsigned mlo = *(const unsigned*)&maskb[mb0 + nt * 8];
                unsigned mhi = *(const unsigned*)&maskb[mb1 + nt * 8];
                e_lo[nt] = ex2h2(hadd2u(packh2(sc[nt][0], sc[nt][1]), mlo));
                e_hi[nt] = ex2h2(hadd2u(packh2(sc[nt][2], sc[nt][3]), mhi));
            }
        }

        // ---- O += P @ V; row sums via ones-column mma ----
#pragma unroll
        for (int ks = 0; ks < 4; ks++) {
            const unsigned a0 = e_lo[2 * ks];
            const unsigned a1 = e_hi[2 * ks];
            const unsigned a2 = e_lo[2 * ks + 1];
            const unsigned a3 = e_hi[2 * ks + 1];
#pragma unroll
            for (int j = 0; j < 4; j++) {
                unsigned b0, b1, b2, b3;
                ldsm4t(b0, b1, b2, b3,
                       sbV + kbufB + (unsigned)((16 * ks * HSTR + j * 16) * 2) + vOff);
                mma_f16(oc[2 * j],     a0, a1, a2, a3, b0, b1);
                mma_f16(oc[2 * j + 1], a0, a1, a2, a3, b2, b3);
            }
            mma_f16(lsum, a0, a1, a2, a3, ub, ub);
        }
        __syncthreads();
    }

    // epilogue: broadcast row sums from c4==0 lanes, normalize, write fp16 ctx
    const int src = lane & ~3;
    const float l0 = __shfl_sync(0xffffffffu, lsum[0], src);
    const float l1 = __shfl_sync(0xffffffffu, lsum[2], src);
    const float il0 = 1.0f / l0, il1 = 1.0f / l1;
    const size_t R0c = base + (size_t)(qb + 16 * w + r4) * HH + hoff;
#pragma unroll
    for (int nt = 0; nt < 8; nt++) {
        const int col = nt * 8 + 2 * c4;
        *(__half2*)&Ctxh[R0c + col] =
            __floats2half2_rn(oc[nt][0] * il0, oc[nt][1] * il0);
        *(__half2*)&Ctxh[R0c + 8 * HH + col] =
            __floats2half2_rn(oc[nt][2] * il1, oc[nt][3] * il1);
    }
}

// ---------------- launch -----------------------------------------------------
extern "C" void kernel_launch(void* const* d_in, const int* in_sizes, int n_in,
                              void* d_out, int out_size)
{
    const float* key   = (const float*)d_in[0];
    const float* value = (const float*)d_in[1];
    const float* query = (const float*)d_in[2];
    const float* mask  = (const float*)d_in[3];
    const float* Wq    = (const float*)d_in[4];
    const float* bq    = (const float*)d_in[5];
    const float* Wk    = (const float*)d_in[6];
    const float* bk    = (const float*)d_in[7];
    const float* Wv    = (const float*)d_in[8];
    const float* bv    = (const float*)d_in[9];
    const float* Wo    = (const float*)d_in[10];
    const float* bo    = (const float*)d_in[11];
    float* out = (float*)d_out;

    __half *qh, *kh, *vh, *ch, *xq, *xk, *xv, *wqh, *wkh, *wvh, *woh, *mh;
    cudaGetSymbolAddress((void**)&qh, g_qh);
    cudaGetSymbolAddress((void**)&kh, g_kh);
    cudaGetSymbolAddress((void**)&vh, g_vh);
    cudaGetSymbolAddress((void**)&ch, g_ch);
    cudaGetSymbolAddress((void**)&xq, g_xq);
    cudaGetSymbolAddress((void**)&xk, g_xk);
    cudaGetSymbolAddress((void**)&xv, g_xv);
    cudaGetSymbolAddress((void**)&wqh, g_wqh);
    cudaGetSymbolAddress((void**)&wkh, g_wkh);
    cudaGetSymbolAddress((void**)&wvh, g_wvh);
    cudaGetSymbolAddress((void**)&woh, g_woh);
    cudaGetSymbolAddress((void**)&mh, g_mh);

    cudaFuncSetAttribute(gemm_qkv,
                         cudaFuncAttributeMaxDynamicSharedMemorySize, GEMM2_SMEM);
    cudaFuncSetAttribute(gemm_out,
                         cudaFuncAttributeMaxDynamicSharedMemorySize, GEMM2_SMEM);
    cudaFuncSetAttribute(flash_f16,
                         cudaFuncAttributeMaxDynamicSharedMemorySize, FLASH_SMEM);

    const int nact4 = MM * HH / 4;          // 1M
    const int nw4 = HH * HH / 4;            // 256K
    const int nmask4 = BB * SS * SS / 4;    // 2M

    // prepass: activations + weights (one launch) and mask (log2e-scaled fp16)
    dim3 cgrid((nact4 + 255) / 256, 7);
    f2h_all<<<cgrid, 256>>>(
        (const float4*)query, (const float4*)key, (const float4*)value,
        (const float4*)Wq, (const float4*)Wk, (const float4*)Wv, (const float4*)Wo,
        (uint2*)xq, (uint2*)xk, (uint2*)xv,
        (uint2*)wqh, (uint2*)wkh, (uint2*)wvh, (uint2*)woh,
        nact4, nw4);
    mask2h<<<(nmask4 + 255) / 256, 256>>>((const float4*)mask, (uint2*)mh, nmask4);

    // fused Q/K/V projections (Q folds 0.125*log2e)
    dim3 qgrid(HH / 128, MM / 128, 3);   // (8, 32, 3)
    gemm_qkv<<<qgrid, 256, GEMM2_SMEM>>>(xq, xk, xv, wqh, wkh, wvh,
                                         bq, bk, bv, qh, kh, vh);

    // attention (fp16, exp2-domain softmax, register-resident P, mma row sums)
    dim3 fgrid(SS / FBQ, NHEADS, BB);    // (16, 16, 2)
    flash_f16<<<fgrid, 256, FLASH_SMEM>>>(qh, kh, vh, mh, ch);

    // output projection (fp16 inputs, fp32 out)
    dim3 ogrid(HH / 128, MM / 128);      // (8, 32)
    gemm_out<<<ogrid, 256, GEMM2_SMEM>>>(ch, woh, bo, out);
}

// round 17
// speedup vs baseline: 1.1809x; 1.1809x over previous
#include <cuda_runtime.h>
#include <cuda_fp16.h>
#include <math.h>

// Problem constants
#define BB 2
#define SS 2048
#define HH 1024
#define NHEADS 16
#define DH 64
#define MM (BB * SS)   // 4096 rows
#define LOG2E 1.44269504088896f

// ---------------- scratch (device globals; no allocation allowed) -----------
__device__ __half g_qh[MM * HH];      // projected Q/K/V (fp16)
__device__ __half g_kh[MM * HH];
__device__ __half g_vh[MM * HH];
__device__ __half g_ch[MM * HH];      // flash output ctx (fp16)
__device__ __half g_xq[MM * HH];      // converted activations
__device__ __half g_xk[MM * HH];
__device__ __half g_xv[MM * HH];
__device__ __half g_wqh[HH * HH];     // converted weights [k][n]
__device__ __half g_wkh[HH * HH];
__device__ __half g_wvh[HH * HH];
__device__ __half g_woh[HH * HH];
__device__ __half g_mh[BB * SS * SS]; // mask * log2e, fp16
__device__ int    g_mnz;              // mask-nonzero flag

// ---------------- helpers ----------------------------------------------------
__device__ __forceinline__ void mma_f16(float c[4],
                                        unsigned a0, unsigned a1,
                                        unsigned a2, unsigned a3,
                                        unsigned b0, unsigned b1) {
    asm volatile(
        "mma.sync.aligned.m16n8k16.row.col.f32.f16.f16.f32 "
        "{%0,%1,%2,%3}, {%4,%5,%6,%7}, {%8,%9}, {%0,%1,%2,%3};"
        : "+f"(c[0]), "+f"(c[1]), "+f"(c[2]), "+f"(c[3])
        : "r"(a0), "r"(a1), "r"(a2), "r"(a3), "r"(b0), "r"(b1));
}

__device__ __forceinline__ void ldsm4(unsigned& d0, unsigned& d1,
                                      unsigned& d2, unsigned& d3, unsigned a) {
    asm volatile("ldmatrix.sync.aligned.m8n8.x4.shared.b16 {%0,%1,%2,%3}, [%4];"
                 : "=r"(d0), "=r"(d1), "=r"(d2), "=r"(d3) : "r"(a));
}
__device__ __forceinline__ void ldsm4t(unsigned& d0, unsigned& d1,
                                       unsigned& d2, unsigned& d3, unsigned a) {
    asm volatile("ldmatrix.sync.aligned.m8n8.x4.trans.shared.b16 {%0,%1,%2,%3}, [%4];"
                 : "=r"(d0), "=r"(d1), "=r"(d2), "=r"(d3) : "r"(a));
}

__device__ __forceinline__ void cpa16(unsigned sdst, const void* gsrc) {
    asm volatile("cp.async.cg.shared.global [%0], [%1], 16;"
                 :: "r"(sdst), "l"(gsrc));
}
__device__ __forceinline__ void cpa_commit() {
    asm volatile("cp.async.commit_group;");
}
__device__ __forceinline__ void cpa_wait1() {
    asm volatile("cp.async.wait_group 1;");
}

__device__ __forceinline__ unsigned packh2(float x, float y) {
    __half2 h = __floats2half2_rn(x, y);
    return *(unsigned*)&h;
}
__device__ __forceinline__ unsigned hadd2u(unsigned a, unsigned b) {
    unsigned d;
    asm("add.f16x2 %0, %1, %2;" : "=r"(d) : "r"(a), "r"(b));
    return d;
}
__device__ __forceinline__ unsigned ex2h2(unsigned a) {
    unsigned d;
    asm("ex2.approx.f16x2 %0, %1;" : "=r"(d) : "r"(a));
    return d;
}

// ---------------- prepass: fp32 -> fp16 (7 tensors, one launch) --------------
__global__ __launch_bounds__(256) void f2h_all(
    const float4* i0, const float4* i1, const float4* i2, const float4* i3,
    const float4* i4, const float4* i5, const float4* i6,
    uint2* o0, uint2* o1, uint2* o2, uint2* o3,
    uint2* o4, uint2* o5, uint2* o6,
    int nact4, int nw4)
{
    const int seg = blockIdx.y;
    const float4* in;
    uint2* out;
    int n4;
    switch (seg) {
        case 0: in = i0; out = o0; n4 = nact4; break;
        case 1: in = i1; out = o1; n4 = nact4; break;
        case 2: in = i2; out = o2; n4 = nact4; break;
        case 3: in = i3; out = o3; n4 = nw4; break;
        case 4: in = i4; out = o4; n4 = nw4; break;
        case 5: in = i5; out = o5; n4 = nw4; break;
        default: in = i6; out = o6; n4 = nw4; break;
    }
    int i = blockIdx.x * 256 + threadIdx.x;
    if (i < n4) {
        float4 v = in[i];
        __half2 h0 = __floats2half2_rn(v.x, v.y);
        __half2 h1 = __floats2half2_rn(v.z, v.w);
        out[i] = make_uint2(*(unsigned*)&h0, *(unsigned*)&h1);
    }
}

__global__ void zero_flag(int* f) { *f = 0; }

// mask -> fp16 pre-scaled by log2e; also detect whether mask has any nonzero
__global__ __launch_bounds__(256) void mask2h(const float4* __restrict__ in,
                                              uint2* __restrict__ out, int n4,
                                              int* __restrict__ flag)
{
    int i = blockIdx.x * 256 + threadIdx.x;
    int nz = 0;
    if (i < n4) {
        float4 v = in[i];
        nz = (v.x != 0.0f) | (v.y != 0.0f) | (v.z != 0.0f) | (v.w != 0.0f);
        __half2 h0 = __floats2half2_rn(v.x * LOG2E, v.y * LOG2E);
        __half2 h1 = __floats2half2_rn(v.z * LOG2E, v.w * LOG2E);
        out[i] = make_uint2(*(unsigned*)&h0, *(unsigned*)&h1);
    }
    if (__syncthreads_or(nz) && threadIdx.x == 0)
        atomicOr(flag, 1);
}

// ---------------- fp16 GEMM body (Round-13 proven) ---------------------------
#define G2BK 32
#define A2STR 40
#define B2STR 136
#define ABUFB (128 * A2STR * 2)
#define BBUFB (G2BK * B2STR * 2)
#define GEMM2_SMEM (2 * ABUFB + 2 * BBUFB)

__device__ __forceinline__ void gemm_body(
    const __half* __restrict__ A, const __half* __restrict__ W,
    const float* __restrict__ bias, float* __restrict__ Cf,
    __half* __restrict__ Ch, float scale)
{
    extern __shared__ __half gsm2[];
    const unsigned sbA = (unsigned)__cvta_generic_to_shared(gsm2);
    const unsigned sbB = sbA + 2 * ABUFB;

    const int tid = threadIdx.x;
    const int lane = tid & 31;
    const int wid = tid >> 5;
    const int wm = (wid & 1) * 64;
    const int wn = (wid >> 1) * 32;
    const int r4 = lane >> 2;
    const int c4 = lane & 3;
    const int bm = blockIdx.y * 128;
    const int bn = blockIdx.x * 128;

    const int arow = tid >> 1;
    const int acol = (tid & 1) * 16;
    const int brow = tid >> 3;
    const int bcol = (tid & 7) * 16;

    const int bsel = lane >> 3;
    const int l7 = lane & 7;
    const unsigned aOff = (unsigned)(((8 * (bsel & 1) + l7) * A2STR + 8 * (bsel >> 1)) * 2);
    const unsigned bOff = (unsigned)(((8 * (bsel & 1) + l7) * B2STR + 8 * (bsel >> 1)) * 2);

    const __half* asrc = &A[(size_t)(bm + arow) * HH + acol];
    const __half* bsrc = &W[(size_t)brow * HH + bn + bcol];

    float acc[16][4];
#pragma unroll
    for (int i = 0; i < 16; i++)
#pragma unroll
        for (int j = 0; j < 4; j++) acc[i][j] = 0.0f;

    const int nk = HH / G2BK;

    {
        const unsigned dA = sbA + (unsigned)((arow * A2STR + acol) * 2);
        const unsigned dB = sbB + (unsigned)((brow * B2STR + bcol) * 2);
        cpa16(dA, asrc);       cpa16(dA + 16, asrc + 8);
        cpa16(dB, bsrc);       cpa16(dB + 16, bsrc + 8);
        cpa_commit();
    }

    for (int kt = 0; kt < nk; kt++) {
        if (kt + 1 < nk) {
            const int k0 = (kt + 1) * G2BK;
            const int nb = (kt + 1) & 1;
            const unsigned dA = sbA + (unsigned)(nb * ABUFB + (arow * A2STR + acol) * 2);
            const unsigned dB = sbB + (unsigned)(nb * BBUFB + (brow * B2STR + bcol) * 2);
            cpa16(dA, asrc + k0);       cpa16(dA + 16, asrc + k0 + 8);
            const __half* bs = &W[(size_t)(k0 + brow) * HH + bn + bcol];
            cpa16(dB, bs);              cpa16(dB + 16, bs + 8);
        }
        cpa_commit();
        cpa_wait1();
        __syncthreads();

        const unsigned abuf = sbA + (unsigned)((kt & 1) * ABUFB);
        const unsigned bbuf = sbB + (unsigned)((kt & 1) * BBUFB);

#pragma unroll
        for (int s = 0; s < 2; s++) {
            unsigned bf[2][4];
#pragma unroll
            for (int p = 0; p < 2; p++)
                ldsm4t(bf[p][0], bf[p][1], bf[p][2], bf[p][3],
                       bbuf + (unsigned)((s * 16 * B2STR + wn + p * 16) * 2) + bOff);
#pragma unroll
            for (int mt = 0; mt < 4; mt++) {
                unsigned a0, a1, a2, a3;
                ldsm4(a0, a1, a2, a3,
                      abuf + (unsigned)(((wm + mt * 16) * A2STR + s * 16) * 2) + aOff);
#pragma unroll
                for (int p = 0; p < 2; p++) {
                    mma_f16(acc[mt * 4 + 2 * p],     a0, a1, a2, a3, bf[p][0], bf[p][1]);
                    mma_f16(acc[mt * 4 + 2 * p + 1], a0, a1, a2, a3, bf[p][2], bf[p][3]);
                }
            }
        }
        __syncthreads();
    }

#pragma unroll
    for (int mt = 0; mt < 4; mt++) {
#pragma unroll
        for (int nt = 0; nt < 4; nt++) {
            const int row0 = bm + wm + mt * 16 + r4;
            const int col = bn + wn + nt * 8 + 2 * c4;
            const float b0 = bias[col], b1 = bias[col + 1];
            float v00 = (acc[mt * 4 + nt][0] + b0) * scale;
            float v01 = (acc[mt * 4 + nt][1] + b1) * scale;
            float v10 = (acc[mt * 4 + nt][2] + b0) * scale;
            float v11 = (acc[mt * 4 + nt][3] + b1) * scale;
            if (Ch) {
                *(__half2*)&Ch[(size_t)row0 * HH + col] = __floats2half2_rn(v00, v01);
                *(__half2*)&Ch[(size_t)(row0 + 8) * HH + col] = __floats2half2_rn(v10, v11);
            } else {
                float* c0 = &Cf[(size_t)row0 * HH + col];
                float* c1 = &Cf[(size_t)(row0 + 8) * HH + col];
                c0[0] = v00; c0[1] = v01;
                c1[0] = v10; c1[1] = v11;
            }
        }
    }
}

// fused Q/K/V projection. Q folds 0.125*log2e (exp2-domain softmax).
__global__ __launch_bounds__(256) void gemm_qkv(
    const __half* Aq, const __half* Ak, const __half* Av,
    const __half* Wq, const __half* Wk, const __half* Wv,
    const float* bq, const float* bk, const float* bv,
    __half* Cq, __half* Ck, __half* Cv)
{
    const int z = blockIdx.z;
    const __half* A = (z == 0) ? Aq : (z == 1) ? Ak : Av;
    const __half* W = (z == 0) ? Wq : (z == 1) ? Wk : Wv;
    const float* bias = (z == 0) ? bq : (z == 1) ? bk : bv;
    __half* C = (z == 0) ? Cq : (z == 1) ? Ck : Cv;
    gemm_body(A, W, bias, nullptr, C, (z == 0) ? 0.125f * LOG2E : 1.0f);
}

__global__ __launch_bounds__(256) void gemm_out(
    const __half* A, const __half* W, const float* bias, float* C)
{
    gemm_body(A, W, bias, C, nullptr, 1.0f);
}

// ---------------- Flash attention (fp16, exp2-domain, mask fast path) --------
// Scores arrive in log2 domain. If the mask is identically zero (runtime flag
// computed by mask2h), the mask loads/adds are skipped entirely — uniform
// branch, mathematically identical result for zero masks.
#define FBQ 128
#define HSTR 72
#define KHALF (64 * HSTR)
#define FLASH_SMEM (4 * KHALF * 2)   // 2 K buffers + 2 V buffers

__global__ __launch_bounds__(256, 2) void flash_f16(
    const __half* __restrict__ Q, const __half* __restrict__ K,
    const __half* __restrict__ V, const __half* __restrict__ maskh,
    const int* __restrict__ mflag, __half* __restrict__ Ctxh)
{
    extern __shared__ __half hsm[];
    const unsigned sbK = (unsigned)__cvta_generic_to_shared(hsm);
    const unsigned sbV = sbK + 2 * KHALF * 2;

    const int tid = threadIdx.x;
    const int lane = tid & 31;
    const int w = tid >> 5;
    const int r4 = lane >> 2;
    const int c4 = lane & 3;
    const int qb = blockIdx.x * FBQ;
    const int h = blockIdx.y;
    const int b = blockIdx.z;

    const size_t base = (size_t)b * SS * HH;
    const int hoff = h * DH;
    const __half* maskb = maskh + (size_t)b * SS * SS;
    const int mnz = *mflag;   // uniform across grid

    const int srow = tid >> 2;
    const int scol = (tid & 3) * 16;

    const int bsel = lane >> 3;
    const int l7 = lane & 7;
    const unsigned kOff = (unsigned)(((8 * (bsel >> 1) + l7) * HSTR + 8 * (bsel & 1)) * 2);
    const unsigned vOff = (unsigned)(((8 * (bsel & 1) + l7) * HSTR + 8 * (bsel >> 1)) * 2);

    // ones-column B fragment for row-sum mma (n==0 column = 1.0)
    const unsigned ub = (r4 == 0) ? 0x3C003C00u : 0u;

    {
        const __half* kp = &K[base + (size_t)srow * HH + hoff + scol];
        const __half* vp = &V[base + (size_t)srow * HH + hoff + scol];
        const unsigned d = (unsigned)((srow * HSTR + scol) * 2);
        cpa16(sbK + d, kp);       cpa16(sbK + d + 16, kp + 8);
        cpa16(sbV + d, vp);       cpa16(sbV + d + 16, vp + 8);
        cpa_commit();
    }

    unsigned qf[4][4];
    {
        const size_t R0 = base + (size_t)(qb + 16 * w + r4) * HH + hoff;
#pragma unroll
        for (int ks = 0; ks < 4; ks++) {
            const int col = 16 * ks + 2 * c4;
            qf[ks][0] = *(const unsigned*)&Q[R0 + col];
            qf[ks][1] = *(const unsigned*)&Q[R0 + 8 * HH + col];
            qf[ks][2] = *(const unsigned*)&Q[R0 + col + 8];
            qf[ks][3] = *(const unsigned*)&Q[R0 + 8 * HH + col + 8];
        }
    }

    float oc[8][4];
#pragma unroll
    for (int nt = 0; nt < 8; nt++)
#pragma unroll
        for (int j = 0; j < 4; j++) oc[nt][j] = 0.0f;
    float lsum[4] = {0.0f, 0.0f, 0.0f, 0.0f};

    const int NT = SS / 64;
    for (int t = 0; t < NT; t++) {
        const int k0 = t * 64;
        const unsigned kbufB = (unsigned)((t & 1) * KHALF * 2);

        if (t + 1 < NT) {
            const unsigned nbB = (unsigned)(((t + 1) & 1) * KHALF * 2);
            const __half* kp = &K[base + (size_t)(k0 + 64 + srow) * HH + hoff + scol];
            const __half* vp = &V[base + (size_t)(k0 + 64 + srow) * HH + hoff + scol];
            const unsigned d = (unsigned)((srow * HSTR + scol) * 2);
            cpa16(sbK + nbB + d, kp);   cpa16(sbK + nbB + d + 16, kp + 8);
            cpa16(sbV + nbB + d, vp);   cpa16(sbV + nbB + d + 16, vp + 8);
        }
        cpa_commit();
        cpa_wait1();
        __syncthreads();

        // ---- S = Q @ K^T (log2 domain) ----
        float sc[8][4];
#pragma unroll
        for (int nt = 0; nt < 8; nt++)
#pragma unroll
            for (int j = 0; j < 4; j++) sc[nt][j] = 0.0f;

#pragma unroll
        for (int ks = 0; ks < 4; ks++) {
#pragma unroll
            for (int j = 0; j < 4; j++) {
                unsigned b0, b1, b2, b3;
                ldsm4(b0, b1, b2, b3,
                      sbK + kbufB + (unsigned)((j * 16 * HSTR + 16 * ks) * 2) + kOff);
                mma_f16(sc[2 * j],     qf[ks][0], qf[ks][1], qf[ks][2], qf[ks][3], b0, b1);
                mma_f16(sc[2 * j + 1], qf[ks][0], qf[ks][1], qf[ks][2], qf[ks][3], b2, b3);
            }
        }

        // ---- pack (+ mask if nonzero) + exp2 in half2 -> P fragments ----
        unsigned e_lo[8], e_hi[8];
        if (mnz) {
            const size_t mb0 = (size_t)(qb + 16 * w + r4) * SS + k0 + 2 * c4;
            const size_t mb1 = mb0 + (size_t)8 * SS;
#pragma unroll
            for (int nt = 0; nt < 8; nt++) {
                unsigned mlo = *(const unsigned*)&maskb[mb0 + nt * 8];
                unsigned mhi = *(const unsigned*)&maskb[mb1 + nt * 8];
                e_lo[nt] = ex2h2(hadd2u(packh2(sc[nt][0], sc[nt][1]), mlo));
                e_hi[nt] = ex2h2(hadd2u(packh2(sc[nt][2], sc[nt][3]), mhi));
            }
        } else {
#pragma unroll
            for (int nt = 0; nt < 8; nt++) {
                e_lo[nt] = ex2h2(packh2(sc[nt][0], sc[nt][1]));
                e_hi[nt] = ex2h2(packh2(sc[nt][2], sc[nt][3]));
            }
        }

        // ---- O += P @ V; row sums via ones-column mma ----
#pragma unroll
        for (int ks = 0; ks < 4; ks++) {
            const unsigned a0 = e_lo[2 * ks];
            const unsigned a1 = e_hi[2 * ks];
            const unsigned a2 = e_lo[2 * ks + 1];
            const unsigned a3 = e_hi[2 * ks + 1];
#pragma unroll
            for (int j = 0; j < 4; j++) {
                unsigned b0, b1, b2, b3;
                ldsm4t(b0, b1, b2, b3,
                       sbV + kbufB + (unsigned)((16 * ks * HSTR + j * 16) * 2) + vOff);
                mma_f16(oc[2 * j],     a0, a1, a2, a3, b0, b1);
                mma_f16(oc[2 * j + 1], a0, a1, a2, a3, b2, b3);
            }
            mma_f16(lsum, a0, a1, a2, a3, ub, ub);
        }
        __syncthreads();
    }

    // epilogue: broadcast row sums from c4==0 lanes, normalize, write fp16 ctx
    const int src = lane & ~3;
    const float l0 = __shfl_sync(0xffffffffu, lsum[0], src);
    const float l1 = __shfl_sync(0xffffffffu, lsum[2], src);
    const float il0 = 1.0f / l0, il1 = 1.0f / l1;
    const size_t R0c = base + (size_t)(qb + 16 * w + r4) * HH + hoff;
#pragma unroll
    for (int nt = 0; nt < 8; nt++) {
        const int col = nt * 8 + 2 * c4;
        *(__half2*)&Ctxh[R0c + col] =
            __floats2half2_rn(oc[nt][0] * il0, oc[nt][1] * il0);
        *(__half2*)&Ctxh[R0c + 8 * HH + col] =
            __floats2half2_rn(oc[nt][2] * il1, oc[nt][3] * il1);
    }
}

// ---------------- launch -----------------------------------------------------
extern "C" void kernel_launch(void* const* d_in, const int* in_sizes, int n_in,
                              void* d_out, int out_size)
{
    const float* key   = (const float*)d_in[0];
    const float* value = (const float*)d_in[1];
    const float* query = (const float*)d_in[2];
    const float* mask  = (const float*)d_in[3];
    const float* Wq    = (const float*)d_in[4];
    const float* bq    = (const float*)d_in[5];
    const float* Wk    = (const float*)d_in[6];
    const float* bk    = (const float*)d_in[7];
    const float* Wv    = (const float*)d_in[8];
    const float* bv    = (const float*)d_in[9];
    const float* Wo    = (const float*)d_in[10];
    const float* bo    = (const float*)d_in[11];
    float* out = (float*)d_out;

    __half *qh, *kh, *vh, *ch, *xq, *xk, *xv, *wqh, *wkh, *wvh, *woh, *mh;
    int* mflag;
    cudaGetSymbolAddress((void**)&qh, g_qh);
    cudaGetSymbolAddress((void**)&kh, g_kh);
    cudaGetSymbolAddress((void**)&vh, g_vh);
    cudaGetSymbolAddress((void**)&ch, g_ch);
    cudaGetSymbolAddress((void**)&xq, g_xq);
    cudaGetSymbolAddress((void**)&xk, g_xk);
    cudaGetSymbolAddress((void**)&xv, g_xv);
    cudaGetSymbolAddress((void**)&wqh, g_wqh);
    cudaGetSymbolAddress((void**)&wkh, g_wkh);
    cudaGetSymbolAddress((void**)&wvh, g_wvh);
    cudaGetSymbolAddress((void**)&woh, g_woh);
    cudaGetSymbolAddress((void**)&mh, g_mh);
    cudaGetSymbolAddress((void**)&mflag, g_mnz);

    cudaFuncSetAttribute(gemm_qkv,
                         cudaFuncAttributeMaxDynamicSharedMemorySize, GEMM2_SMEM);
    cudaFuncSetAttribute(gemm_out,
                         cudaFuncAttributeMaxDynamicSharedMemorySize, GEMM2_SMEM);
    cudaFuncSetAttribute(flash_f16,
                         cudaFuncAttributeMaxDynamicSharedMemorySize, FLASH_SMEM);

    const int nact4 = MM * HH / 4;          // 1M
    const int nw4 = HH * HH / 4;            // 256K
    const int nmask4 = BB * SS * SS / 4;    // 2M

    // prepass: activations + weights; mask (log2e-scaled fp16 + nonzero flag)
    zero_flag<<<1, 1>>>(mflag);
    dim3 cgrid((nact4 + 255) / 256, 7);
    f2h_all<<<cgrid, 256>>>(
        (const float4*)query, (const float4*)key, (const float4*)value,
        (const float4*)Wq, (const float4*)Wk, (const float4*)Wv, (const float4*)Wo,
        (uint2*)xq, (uint2*)xk, (uint2*)xv,
        (uint2*)wqh, (uint2*)wkh, (uint2*)wvh, (uint2*)woh,
        nact4, nw4);
    mask2h<<<(nmask4 + 255) / 256, 256>>>((const float4*)mask, (uint2*)mh,
                                          nmask4, mflag);

    // fused Q/K/V projections (Q folds 0.125*log2e)
    dim3 qgrid(HH / 128, MM / 128, 3);   // (8, 32, 3)
    gemm_qkv<<<qgrid, 256, GEMM2_SMEM>>>(xq, xk, xv, wqh, wkh, wvh,
                                         bq, bk, bv, qh, kh, vh);

    // attention (fp16, exp2-domain, mask fast path)
    dim3 fgrid(SS / FBQ, NHEADS, BB);    // (16, 16, 2)
    flash_f16<<<fgrid, 256, FLASH_SMEM>>>(qh, kh, vh, mh, mflag, ch);

    // output projection (fp16 inputs, fp32 out)
    dim3 ogrid(HH / 128, MM / 128);      // (8, 32)
    gemm_out<<<ogrid, 256, GEMM2_SMEM>>>(ch, woh, bo, out);
}